// round 12
// baseline (speedup 1.0000x reference)
#include <cuda_runtime.h>
#include <cuda_bf16.h>

// PrecisionFocusedLoss: mean over B of ce(logits, t) * (1 + 3*penalty(t, argmax))
// C = 2:
//   u  = x1 - x0
//   ce = softplus(t ? -u : u)
//   w  : t=0: u>0 -> 16 (FP), else 1.3 ; t=1: u>0 -> 1.3, else 4 (FN)
// tie (u == 0) -> pred = 0 (strict u > 0).
//
// R12: block-CONTIGUOUS partitioning (vs grid-interleaved). Block b owns
// one contiguous slice of the pair domain (4096 pairs = 96 KB combined for
// B=8.4M), so each SM issues long sequential DRAM streams — max page/row
// locality per channel. Everything else identical to the converged R10/R11
// kernel (lane-contiguous float4+int2 loads, U=4, partials epilogue).

#define NBLOCKS 1024
#define NTHREADS 256
#define U 4                              // pairs per thread per inner iter

__device__ double g_partials[NBLOCKS];
__device__ unsigned int g_done_count;    // zero-init; reset by finalizer

#define W_LOW  1.3000000119209290f       // 1 + 3*0.1 in f32 rounding
#define W_FN   4.0f
#define W_FP   16.0f

__device__ __forceinline__ float sample_loss(float x0, float x1, int t) {
    float u = x1 - x0;
    float z = t ? -u : u;
    float e = __expf(-fabsf(z));
    float ce = fmaxf(z, 0.0f) + __logf(1.0f + e);
    float w;
    if (t) w = (u > 0.0f) ? W_LOW : W_FN;
    else   w = (u > 0.0f) ? W_FP  : W_LOW;
    return ce * w;
}

__global__ void __launch_bounds__(NTHREADS)
loss_fused(const float4* __restrict__ l4, const int2* __restrict__ t2,
           int npairs, const float* __restrict__ logits,
           const int* __restrict__ targets, int n, float* __restrict__ out) {
    float acc = 0.0f;

    // ── Block-contiguous slice: [start, end) of the pair domain ──
    const int ppb   = (npairs + gridDim.x - 1) / gridDim.x;  // pairs per block
    const int start = blockIdx.x * ppb;
    const int end   = min(start + ppb, npairs);

    // Full U-unrolled inner chunks (lane-contiguous within the slice).
    int i = start;
    for (; i + NTHREADS * U <= end; i += NTHREADS * U) {
        int i0 = i + threadIdx.x;
        float4 L[U];
        int2   T[U];
        #pragma unroll
        for (int k = 0; k < U; k++) L[k] = l4[i0 + k * NTHREADS];
        #pragma unroll
        for (int k = 0; k < U; k++) T[k] = t2[i0 + k * NTHREADS];
        #pragma unroll
        for (int k = 0; k < U; k++) {
            acc += sample_loss(L[k].x, L[k].y, T[k].x);
            acc += sample_loss(L[k].z, L[k].w, T[k].y);
        }
    }
    // Remainder pairs within the slice (empty for B = 8388608).
    for (int p = i + threadIdx.x; p < end; p += NTHREADS) {
        float4 L = l4[p];
        int2   T = t2[p];
        acc += sample_loss(L.x, L.y, T.x);
        acc += sample_loss(L.z, L.w, T.y);
    }
    // Scalar tail (n odd) — one thread.
    if (blockIdx.x == 0 && threadIdx.x == 0) {
        for (int s = npairs * 2; s < n; s++)
            acc += sample_loss(logits[2 * s], logits[2 * s + 1], targets[s]);
    }

    // ── Block reduction ──
    __shared__ float warp_sums[NTHREADS / 32];
    #pragma unroll
    for (int o = 16; o > 0; o >>= 1)
        acc += __shfl_down_sync(0xffffffffu, acc, o);
    if ((threadIdx.x & 31) == 0)
        warp_sums[threadIdx.x >> 5] = acc;
    __syncthreads();

    __shared__ bool is_last;
    if (threadIdx.x == 0) {
        float v = 0.0f;
        #pragma unroll
        for (int k = 0; k < NTHREADS / 32; k++) v += warp_sums[k];
        g_partials[blockIdx.x] = (double)v;
        __threadfence();                       // partial visible before bump
        unsigned int c = atomicAdd(&g_done_count, 1u);
        is_last = (c == gridDim.x - 1);
    }
    __syncthreads();

    // ── Last block finalizes (deterministic fixed-order sum) ──
    if (is_last) {
        __shared__ double dsum[NTHREADS / 32];
        double v = 0.0;
        #pragma unroll
        for (int k = threadIdx.x; k < NBLOCKS; k += NTHREADS)
            v += g_partials[k];
        #pragma unroll
        for (int o = 16; o > 0; o >>= 1)
            v += __shfl_down_sync(0xffffffffu, v, o);
        if ((threadIdx.x & 31) == 0)
            dsum[threadIdx.x >> 5] = v;
        __syncthreads();
        if (threadIdx.x < 32) {
            double s = (threadIdx.x < NTHREADS / 32) ? dsum[threadIdx.x] : 0.0;
            #pragma unroll
            for (int o = (NTHREADS / 32) / 2; o > 0; o >>= 1)
                s += __shfl_down_sync(0xffffffffu, s, o);
            if (threadIdx.x == 0) {
                out[0] = (float)(s / (double)n);
                g_done_count = 0;              // reset for next graph replay
            }
        }
    }
}

extern "C" void kernel_launch(void* const* d_in, const int* in_sizes, int n_in,
                              void* d_out, int out_size) {
    const float* logits  = (const float*)d_in[0];   // (B, 2) f32
    const int*   targets = (const int*)d_in[1];     // (B,)   i32
    const int    n  = in_sizes[1];
    const int    npairs = n >> 1;                   // 2 samples per pair

    loss_fused<<<NBLOCKS, NTHREADS>>>(
        (const float4*)logits, (const int2*)targets, npairs, logits, targets,
        n, (float*)d_out);
}

// round 13
// speedup vs baseline: 1.1165x; 1.1165x over previous
#include <cuda_runtime.h>
#include <cuda_bf16.h>

// PrecisionFocusedLoss: mean over B of ce(logits, t) * (1 + 3*penalty(t, argmax))
// C = 2:
//   u  = x1 - x0
//   ce = softplus(t ? -u : u)          (= -log_softmax[target])
//   w  : t=0: u>0 -> 16 (FP), else 1.3 ; t=1: u>0 -> 1.3, else 4 (FN)
// tie (u == 0) -> pred = 0 (strict u > 0).
//
// FINAL / CONVERGED (permanent). Purely DRAM/LTS-bound at ~6.8 TB/s
// effective (B300 LTS cap, ~85% of HBM spec). Controlled experiments:
//  - occupancy 45-81%, MLP 3/6, grid 592/1024, epilogue styles: all flat
//  - L1tex wavefronts cut 40% (21.8%->13.4%): flat => L1tex non-binding
//  - 64B lane strides (R3): -55% REGRESSION => keep <=32B strides
//  - block-contiguous partitioning (R12): -13% REGRESSION => keep
//    grid-interleaved lockstep chunking (dense in-flight address window)
// Traffic (12 B/sample, read-once) is irreducible.
//
// Layout: lane-contiguous loads — each thread takes 2 samples per
// (float4 logits, int2 targets) pair at the same index; every LDG covers
// fully-utilized sectors (float4 -> 4 lines/warp, int2 -> 2). Unroll 4
// front-batches 8 independent loads (96 B in flight/thread), chunks
// grid-interleaved. Epilogue: per-block double partial, fenced counter,
// last block tree-reduces partials in fixed index order (deterministic)
// and resets the counter for graph replay.

#define NBLOCKS 1024
#define NTHREADS 256
#define U 4                              // pairs per thread per outer iter

__device__ double g_partials[NBLOCKS];
__device__ unsigned int g_done_count;    // zero-init; reset by finalizer

#define W_LOW  1.3000000119209290f       // 1 + 3*0.1 in f32 rounding
#define W_FN   4.0f
#define W_FP   16.0f

__device__ __forceinline__ float sample_loss(float x0, float x1, int t) {
    float u = x1 - x0;
    float z = t ? -u : u;
    float e = __expf(-fabsf(z));
    float ce = fmaxf(z, 0.0f) + __logf(1.0f + e);
    float w;
    if (t) w = (u > 0.0f) ? W_LOW : W_FN;
    else   w = (u > 0.0f) ? W_FP  : W_LOW;
    return ce * w;
}

__global__ void __launch_bounds__(NTHREADS)
loss_fused(const float4* __restrict__ l4, const int2* __restrict__ t2,
           int npairs, const float* __restrict__ logits,
           const int* __restrict__ targets, int n, float* __restrict__ out) {
    float acc = 0.0f;

    // ── Bulk: grid-interleaved chunks of NBLOCKS*NTHREADS*U pairs ──
    const int chunk = gridDim.x * blockDim.x * U;
    const int nfull = npairs / chunk;               // full grid-chunks
    for (int c = 0; c < nfull; c++) {
        int i0 = c * chunk + blockIdx.x * (blockDim.x * U) + threadIdx.x;
        float4 L[U];
        int2   T[U];
        #pragma unroll
        for (int k = 0; k < U; k++) L[k] = l4[i0 + k * NTHREADS];
        #pragma unroll
        for (int k = 0; k < U; k++) T[k] = t2[i0 + k * NTHREADS];
        #pragma unroll
        for (int k = 0; k < U; k++) {
            acc += sample_loss(L[k].x, L[k].y, T[k].x);
            acc += sample_loss(L[k].z, L[k].w, T[k].y);
        }
    }

    // ── Remainder pairs (generic; empty for n = 8388608) ──
    for (int p = nfull * chunk + blockIdx.x * blockDim.x + threadIdx.x;
         p < npairs; p += gridDim.x * blockDim.x) {
        float4 L = l4[p];
        int2   T = t2[p];
        acc += sample_loss(L.x, L.y, T.x);
        acc += sample_loss(L.z, L.w, T.y);
    }
    // ── Scalar tail (n odd) — one thread ──
    if (blockIdx.x == 0 && threadIdx.x == 0) {
        for (int i = npairs * 2; i < n; i++)
            acc += sample_loss(logits[2 * i], logits[2 * i + 1], targets[i]);
    }

    // ── Block reduction ──
    __shared__ float warp_sums[NTHREADS / 32];
    #pragma unroll
    for (int o = 16; o > 0; o >>= 1)
        acc += __shfl_down_sync(0xffffffffu, acc, o);
    if ((threadIdx.x & 31) == 0)
        warp_sums[threadIdx.x >> 5] = acc;
    __syncthreads();

    __shared__ bool is_last;
    if (threadIdx.x == 0) {
        float v = 0.0f;
        #pragma unroll
        for (int i = 0; i < NTHREADS / 32; i++) v += warp_sums[i];
        g_partials[blockIdx.x] = (double)v;
        __threadfence();                       // partial visible before bump
        unsigned int c = atomicAdd(&g_done_count, 1u);
        is_last = (c == gridDim.x - 1);
    }
    __syncthreads();

    // ── Last block finalizes (deterministic fixed-order sum) ──
    if (is_last) {
        __shared__ double dsum[NTHREADS / 32];
        double v = 0.0;
        #pragma unroll
        for (int i = threadIdx.x; i < NBLOCKS; i += NTHREADS)
            v += g_partials[i];
        #pragma unroll
        for (int o = 16; o > 0; o >>= 1)
            v += __shfl_down_sync(0xffffffffu, v, o);
        if ((threadIdx.x & 31) == 0)
            dsum[threadIdx.x >> 5] = v;
        __syncthreads();
        if (threadIdx.x < 32) {
            double s = (threadIdx.x < NTHREADS / 32) ? dsum[threadIdx.x] : 0.0;
            #pragma unroll
            for (int o = (NTHREADS / 32) / 2; o > 0; o >>= 1)
                s += __shfl_down_sync(0xffffffffu, s, o);
            if (threadIdx.x == 0) {
                out[0] = (float)(s / (double)n);
                g_done_count = 0;              // reset for next graph replay
            }
        }
    }
}

extern "C" void kernel_launch(void* const* d_in, const int* in_sizes, int n_in,
                              void* d_out, int out_size) {
    const float* logits  = (const float*)d_in[0];   // (B, 2) f32
    const int*   targets = (const int*)d_in[1];     // (B,)   i32
    const int    n  = in_sizes[1];
    const int    npairs = n >> 1;                   // 2 samples per pair

    loss_fused<<<NBLOCKS, NTHREADS>>>(
        (const float4*)logits, (const int2*)targets, npairs, logits, targets,
        n, (float*)d_out);
}

// round 14
// speedup vs baseline: 1.1532x; 1.0328x over previous
#include <cuda_runtime.h>
#include <cuda_bf16.h>

// PrecisionFocusedLoss: mean over B of ce(logits, t) * (1 + 3*penalty(t, argmax))
// C = 2:
//   u  = x1 - x0
//   ce = softplus(t ? -u : u)          (= -log_softmax[target])
//   w  : t=0: u>0 -> 16 (FP), else 1.3 ; t=1: u>0 -> 1.3, else 4 (FN)
// tie (u == 0) -> pred = 0 (strict u > 0).
//
// FINAL / CONVERGED (permanent, resubmission of the record holder).
// Purely DRAM/LTS-bound at ~6.8 TB/s effective (B300 LTS cap, ~85% of
// HBM spec). Controlled experiments:
//  - occupancy 45-85%, MLP 3/6, grid 592/1024, epilogue styles: all flat
//  - L1tex wavefronts cut 40% (21.8%->13.4%): flat => L1tex non-binding
//  - 64B lane strides (R3): -55% REGRESSION => keep <=32B strides
//  - block-contiguous partitioning (R12): -13% REGRESSION => keep
//    grid-interleaved lockstep chunking (dense in-flight address window)
// Traffic (12 B/sample, read-once) is irreducible. Measured noise band
// for identical binaries: +-0.3us.
//
// Layout: lane-contiguous loads — each thread takes 2 samples per
// (float4 logits, int2 targets) pair at the same index; every LDG covers
// fully-utilized sectors (float4 -> 4 lines/warp, int2 -> 2). Unroll 4
// front-batches 8 independent loads (96 B in flight/thread), chunks
// grid-interleaved. Epilogue: per-block double partial, fenced counter,
// last block tree-reduces partials in fixed index order (deterministic)
// and resets the counter for graph replay.

#define NBLOCKS 1024
#define NTHREADS 256
#define U 4                              // pairs per thread per outer iter

__device__ double g_partials[NBLOCKS];
__device__ unsigned int g_done_count;    // zero-init; reset by finalizer

#define W_LOW  1.3000000119209290f       // 1 + 3*0.1 in f32 rounding
#define W_FN   4.0f
#define W_FP   16.0f

__device__ __forceinline__ float sample_loss(float x0, float x1, int t) {
    float u = x1 - x0;
    float z = t ? -u : u;
    float e = __expf(-fabsf(z));
    float ce = fmaxf(z, 0.0f) + __logf(1.0f + e);
    float w;
    if (t) w = (u > 0.0f) ? W_LOW : W_FN;
    else   w = (u > 0.0f) ? W_FP  : W_LOW;
    return ce * w;
}

__global__ void __launch_bounds__(NTHREADS)
loss_fused(const float4* __restrict__ l4, const int2* __restrict__ t2,
           int npairs, const float* __restrict__ logits,
           const int* __restrict__ targets, int n, float* __restrict__ out) {
    float acc = 0.0f;

    // ── Bulk: grid-interleaved chunks of NBLOCKS*NTHREADS*U pairs ──
    const int chunk = gridDim.x * blockDim.x * U;
    const int nfull = npairs / chunk;               // full grid-chunks
    for (int c = 0; c < nfull; c++) {
        int i0 = c * chunk + blockIdx.x * (blockDim.x * U) + threadIdx.x;
        float4 L[U];
        int2   T[U];
        #pragma unroll
        for (int k = 0; k < U; k++) L[k] = l4[i0 + k * NTHREADS];
        #pragma unroll
        for (int k = 0; k < U; k++) T[k] = t2[i0 + k * NTHREADS];
        #pragma unroll
        for (int k = 0; k < U; k++) {
            acc += sample_loss(L[k].x, L[k].y, T[k].x);
            acc += sample_loss(L[k].z, L[k].w, T[k].y);
        }
    }

    // ── Remainder pairs (generic; empty for n = 8388608) ──
    for (int p = nfull * chunk + blockIdx.x * blockDim.x + threadIdx.x;
         p < npairs; p += gridDim.x * blockDim.x) {
        float4 L = l4[p];
        int2   T = t2[p];
        acc += sample_loss(L.x, L.y, T.x);
        acc += sample_loss(L.z, L.w, T.y);
    }
    // ── Scalar tail (n odd) — one thread ──
    if (blockIdx.x == 0 && threadIdx.x == 0) {
        for (int i = npairs * 2; i < n; i++)
            acc += sample_loss(logits[2 * i], logits[2 * i + 1], targets[i]);
    }

    // ── Block reduction ──
    __shared__ float warp_sums[NTHREADS / 32];
    #pragma unroll
    for (int o = 16; o > 0; o >>= 1)
        acc += __shfl_down_sync(0xffffffffu, acc, o);
    if ((threadIdx.x & 31) == 0)
        warp_sums[threadIdx.x >> 5] = acc;
    __syncthreads();

    __shared__ bool is_last;
    if (threadIdx.x == 0) {
        float v = 0.0f;
        #pragma unroll
        for (int i = 0; i < NTHREADS / 32; i++) v += warp_sums[i];
        g_partials[blockIdx.x] = (double)v;
        __threadfence();                       // partial visible before bump
        unsigned int c = atomicAdd(&g_done_count, 1u);
        is_last = (c == gridDim.x - 1);
    }
    __syncthreads();

    // ── Last block finalizes (deterministic fixed-order sum) ──
    if (is_last) {
        __shared__ double dsum[NTHREADS / 32];
        double v = 0.0;
        #pragma unroll
        for (int i = threadIdx.x; i < NBLOCKS; i += NTHREADS)
            v += g_partials[i];
        #pragma unroll
        for (int o = 16; o > 0; o >>= 1)
            v += __shfl_down_sync(0xffffffffu, v, o);
        if ((threadIdx.x & 31) == 0)
            dsum[threadIdx.x >> 5] = v;
        __syncthreads();
        if (threadIdx.x < 32) {
            double s = (threadIdx.x < NTHREADS / 32) ? dsum[threadIdx.x] : 0.0;
            #pragma unroll
            for (int o = (NTHREADS / 32) / 2; o > 0; o >>= 1)
                s += __shfl_down_sync(0xffffffffu, s, o);
            if (threadIdx.x == 0) {
                out[0] = (float)(s / (double)n);
                g_done_count = 0;              // reset for next graph replay
            }
        }
    }
}

extern "C" void kernel_launch(void* const* d_in, const int* in_sizes, int n_in,
                              void* d_out, int out_size) {
    const float* logits  = (const float*)d_in[0];   // (B, 2) f32
    const int*   targets = (const int*)d_in[1];     // (B,)   i32
    const int    n  = in_sizes[1];
    const int    npairs = n >> 1;                   // 2 samples per pair

    loss_fused<<<NBLOCKS, NTHREADS>>>(
        (const float4*)logits, (const int2*)targets, npairs, logits, targets,
        n, (float*)d_out);
}